// round 9
// baseline (speedup 1.0000x reference)
#include <cuda_runtime.h>

// ---------------------------------------------------------------------------
// DataReUploadingLinear, Round 7:
//  * cmm: manual double-buffered software pipeline (2-k stages), 4x2
//    warp-uniform tile. Loads for stage n+1 issued before FMAs of stage n.
//  * ONE cmm body driven by a 12-step descriptor table (constant memory):
//    SASS shrinks ~40KB -> ~5KB, fits L0 I-cache; regs freed for pipelining.
//  * expm: s=6 + degree-16 Paterson-Stockmeyer (12 matmuls).
//  * Persistent CTAs + job counter; circuit fused via flag spin.
// ---------------------------------------------------------------------------

#define DIM      64
#define NPAULI   4096
#define S        68                  // smem row stride (rows 16B-aligned)
#define PL       (64 * S)            // plane floats (4352)
#define NTHREADS 512
#define INV_SCALE (1.0f / 64.0f)     // 1 / 2^s, s = 6
#define GRID     152

typedef unsigned long long u64;

__device__ float2 g_Up[4][DIM * DIM];
__device__ int    g_flag;            // finished param jobs
__device__ int    g_ctr;             // persistent job counter

// 12 matmul steps: {Xr,Xi, Yr,Yi, Zr,Zi, withg} as plane indices
// planes: 0=Ar 1=Ai 2=A2r 3=A2i 4=A3r 5=A3i 6=A4r 7=A4i 8=Br 9=Bi 10=Cr 11=Ci
__constant__ signed char c_ix[12][7] = {
    { 0, 1,  0, 1,  2, 3, 0},   // A2 = A*A
    { 0, 1,  2, 3,  4, 5, 0},   // A3 = A*A2
    { 2, 3,  2, 3,  6, 7, 0},   // A4 = A2*A2
    { 6, 7,  8, 9, 10,11, 1},   // C = G2 + A4*B
    { 6, 7, 10,11,  8, 9, 1},   // B = G1 + A4*C
    { 6, 7,  8, 9, 10,11, 1},   // C = G0 + A4*B
    {10,11, 10,11,  8, 9, 0},   // squarings (6): ends in C
    { 8, 9,  8, 9, 10,11, 0},
    {10,11, 10,11,  8, 9, 0},
    { 8, 9,  8, 9, 10,11, 0},
    {10,11, 10,11,  8, 9, 0},
    { 8, 9,  8, 9, 10,11, 0},
};
__constant__ float c_cf[12][4] = {
    {0,0,0,0}, {0,0,0,0}, {0,0,0,0},
    {2.48015873e-5f, 2.75573192e-6f, 2.75573192e-7f, 2.50521084e-8f},  // G2
    {4.16666667e-2f, 8.33333333e-3f, 1.38888889e-3f, 1.98412698e-4f},  // G1
    {1.f, 1.f, 0.5f, 1.f / 6.f},                                       // G0
    {0,0,0,0}, {0,0,0,0}, {0,0,0,0}, {0,0,0,0}, {0,0,0,0}, {0,0,0,0},
};

__device__ __forceinline__ u64 pk2(float lo, float hi) {
    u64 r; asm("mov.b64 %0, {%1, %2};" : "=l"(r) : "f"(lo), "f"(hi)); return r;
}
__device__ __forceinline__ u64 f2fma(u64 a, u64 b, u64 c) {
    u64 d; asm("fma.rn.f32x2 %0, %1, %2, %3;" : "=l"(d) : "l"(a), "l"(b), "l"(c));
    return d;
}
__device__ __forceinline__ u64 f2sub(u64 a, u64 b) {
    float al, ah, bl, bh;
    asm("mov.b64 {%0, %1}, %2;" : "=f"(al), "=f"(ah) : "l"(a));
    asm("mov.b64 {%0, %1}, %2;" : "=f"(bl), "=f"(bh) : "l"(b));
    return pk2(al - bl, ah - bh);
}

// Z = [G(A)] + X*Y, complex 64x64 in smem planes (stride S). 512 threads.
// Tile: 4 rows (warp-uniform) x 2 cols (per-lane). Double-buffered pipeline
// over 2-k stages; wrap-load keeps the loop branch-free.
__device__ __forceinline__ void cmm_body(
    const float* Xr, const float* Xi,
    const float* Yr, const float* Yi,
    float* Zr, float* Zi,
    const float* Ar, const float* Ai,
    const float* A2r, const float* A2i,
    const float* A3r, const float* A3i,
    int withg, float c0, float c1, float c2, float c3)
{
    const int tid = threadIdx.x;
    const int i0 = (tid >> 5) * 4;        // warp-uniform row group
    const int j0 = (tid & 31) * 2;        // per-lane column pair

    u64 crp[4], crn[4], cim[4];
    if (withg) {
#pragma unroll
        for (int a = 0; a < 4; a++) {
            const int i = i0 + a;
            const int o0 = i * S + j0, o1 = o0 + 1;
            float g0r = c1 * Ar[o0] + c2 * A2r[o0] + c3 * A3r[o0]
                      + ((i == j0)     ? c0 : 0.f);
            float g1r = c1 * Ar[o1] + c2 * A2r[o1] + c3 * A3r[o1]
                      + ((i == j0 + 1) ? c0 : 0.f);
            float g0i = c1 * Ai[o0] + c2 * A2i[o0] + c3 * A3i[o0];
            float g1i = c1 * Ai[o1] + c2 * A2i[o1] + c3 * A3i[o1];
            crp[a] = pk2(g0r, g1r);
            cim[a] = pk2(g0i, g1i);
            crn[a] = 0ull;
        }
    } else {
#pragma unroll
        for (int a = 0; a < 4; a++) { crp[a] = 0ull; crn[a] = 0ull; cim[a] = 0ull; }
    }

    float2 xrA[4], xiA[4], xrB[4], xiB[4];
    u64 yrA[2], yiA[2], yrB[2], yiB[2];

    // prologue: stage A = k {0,1}
#pragma unroll
    for (int a = 0; a < 4; a++) {
        xrA[a] = *(const float2*)&Xr[(i0 + a) * S];
        xiA[a] = *(const float2*)&Xi[(i0 + a) * S];
    }
    yrA[0] = *(const u64*)&Yr[0 * S + j0];
    yrA[1] = *(const u64*)&Yr[1 * S + j0];
    yiA[0] = *(const u64*)&Yi[0 * S + j0];
    yiA[1] = *(const u64*)&Yi[1 * S + j0];

#pragma unroll 1
    for (int k = 0; k < 64; k += 4) {
        // prefetch stage B = {k+2, k+3}
        {
            const int kn = k + 2;
#pragma unroll
            for (int a = 0; a < 4; a++) {
                xrB[a] = *(const float2*)&Xr[(i0 + a) * S + kn];
                xiB[a] = *(const float2*)&Xi[(i0 + a) * S + kn];
            }
            yrB[0] = *(const u64*)&Yr[kn * S + j0];
            yrB[1] = *(const u64*)&Yr[(kn + 1) * S + j0];
            yiB[0] = *(const u64*)&Yi[kn * S + j0];
            yiB[1] = *(const u64*)&Yi[(kn + 1) * S + j0];
        }
        // compute stage A = {k, k+1}
#pragma unroll
        for (int kk = 0; kk < 2; kk++)
#pragma unroll
            for (int a = 0; a < 4; a++) {
                const float xr = kk ? xrA[a].y : xrA[a].x;
                const float xi = kk ? xiA[a].y : xiA[a].x;
                const u64 xrr = pk2(xr, xr);
                const u64 xii = pk2(xi, xi);
                crp[a] = f2fma(xrr, yrA[kk], crp[a]);
                crn[a] = f2fma(xii, yiA[kk], crn[a]);
                cim[a] = f2fma(xrr, yiA[kk], cim[a]);
                cim[a] = f2fma(xii, yrA[kk], cim[a]);
            }
        // prefetch stage A = {k+4, k+5} (wraps harmlessly at k=60)
        {
            const int kn = (k + 4) & 63;
#pragma unroll
            for (int a = 0; a < 4; a++) {
                xrA[a] = *(const float2*)&Xr[(i0 + a) * S + kn];
                xiA[a] = *(const float2*)&Xi[(i0 + a) * S + kn];
            }
            yrA[0] = *(const u64*)&Yr[kn * S + j0];
            yrA[1] = *(const u64*)&Yr[(kn + 1) * S + j0];
            yiA[0] = *(const u64*)&Yi[kn * S + j0];
            yiA[1] = *(const u64*)&Yi[(kn + 1) * S + j0];
        }
        // compute stage B = {k+2, k+3}
#pragma unroll
        for (int kk = 0; kk < 2; kk++)
#pragma unroll
            for (int a = 0; a < 4; a++) {
                const float xr = kk ? xrB[a].y : xrB[a].x;
                const float xi = kk ? xiB[a].y : xiB[a].x;
                const u64 xrr = pk2(xr, xr);
                const u64 xii = pk2(xi, xi);
                crp[a] = f2fma(xrr, yrB[kk], crp[a]);
                crn[a] = f2fma(xii, yiB[kk], crn[a]);
                cim[a] = f2fma(xrr, yiB[kk], cim[a]);
                cim[a] = f2fma(xii, yrB[kk], cim[a]);
            }
    }

#pragma unroll
    for (int a = 0; a < 4; a++) {
        *(u64*)&Zr[(i0 + a) * S + j0] = f2sub(crp[a], crn[a]);
        *(u64*)&Zi[(i0 + a) * S + j0] = cim[a];
    }
}

__global__ void reset_kernel() { g_flag = 0; g_ctr = 0; }

// Persistent: job < nreps -> build Up[job]; else build Ud for sample
// (job - nreps), wait for all Up, run circuit, write out.
__global__ __launch_bounds__(NTHREADS, 1)
void build_kernel(const float* __restrict__ x,
                  const float* __restrict__ weight,
                  const float* __restrict__ bias,
                  float* __restrict__ out,
                  int nreps, int njobs)
{
    extern __shared__ float sm[];
    float* P12[12];
#pragma unroll
    for (int p = 0; p < 12; p++) P12[p] = sm + p * PL;
    float* Ar  = P12[0];  float* Ai  = P12[1];
    float* A2r = P12[2];  float* A2i = P12[3];
    float* A3r = P12[4];  float* A3i = P12[5];
    float* A4r = P12[6];  float* A4i = P12[7];
    float* Br  = P12[8];  float* Bi  = P12[9];
    float* Cr  = P12[10]; float* Ci  = P12[11];
    __shared__ float2 psiA[DIM], psiB[DIM];
    __shared__ int s_job;

    const int tid = threadIdx.x;

    for (;;) {
        __syncthreads();                    // smem reuse + s_job protect
        if (tid == 0) s_job = atomicAdd(&g_ctr, 1);
        __syncthreads();
        const int job = s_job;
        if (job >= njobs) return;
        const bool is_param = (job < nreps);

        // ---- 1. Pauli coefficients into Br[0..4095] ----
        if (is_param) {
            const float* wrow = weight + (size_t)job * (NPAULI - 1);
            for (int p = tid; p < NPAULI; p += NTHREADS)
                Br[p] = (p == 0) ? 0.f : wrow[p - 1];
        } else {
            const float* xrow = x + (size_t)(job - nreps) * 4000;
            for (int p = tid; p < NPAULI; p += NTHREADS)
                Br[p] = (p < 4000) ? xrow[p] : 0.f;
        }
        __syncthreads();

        // ---- 2. D[m][t] = coef(p(m,t)) * (-i)^popc(t&m) ----
        for (int idx = tid; idx < NPAULI; idx += NTHREADS) {
            const int m = idx >> 6, t = idx & 63;
            const int mt = m ^ t;
            int p = 0;
#pragma unroll
            for (int k = 0; k < 6; k++)
                p |= (((mt >> k) & 1) << (2 * k)) | (((t >> k) & 1) << (2 * k + 1));
            const float v = Br[p];
            const int c = __popc(t & m) & 3;
            float re, im;
            switch (c) {
                case 0:  re =  v; im = 0.f; break;
                case 1:  re = 0.f; im = -v; break;
                case 2:  re = -v; im = 0.f; break;
                default: re = 0.f; im =  v; break;
            }
            Cr[idx] = re; Ci[idx] = im;
        }
        __syncthreads();

        // ---- 3. 64-pt WHT over t for each m ----
        for (int s = 0; s < 6; s++) {
            const int half = 1 << s;
            for (int n = tid; n < 2048; n += NTHREADS) {
                const int m = n >> 5, r = n & 31;
                const int t0 = ((r >> s) << (s + 1)) | (r & (half - 1));
                const int a0 = m * 64 + t0, a1 = a0 + half;
                const float ur = Cr[a0], ui = Ci[a0];
                const float vr = Cr[a1], vi = Ci[a1];
                Cr[a0] = ur + vr; Ci[a0] = ui + vi;
                Cr[a1] = ur - vr; Ci[a1] = ui - vi;
            }
            __syncthreads();
        }

        // ---- 4. A = -i*H/2^s :  H[i][i^m] = W[m][i] ----
        for (int idx = tid; idx < NPAULI; idx += NTHREADS) {
            const int m = idx >> 6, i = idx & 63;
            const int j = i ^ m;
            const float hr = Cr[m * 64 + i], hi = Ci[m * 64 + i];
            Ar[i * S + j] =  hi * INV_SCALE;
            Ai[i * S + j] = -hr * INV_SCALE;
        }
        __syncthreads();

        // ---- 5. the 12 matmuls, table-driven (one cmm body in SASS) ----
#pragma unroll 1
        for (int st = 0; st < 12; st++) {
            if (st == 3) {
                // G3 = I/12! + A/13! + A2/14! + A3/15! + A4/16!  -> B
                const float c0 = 2.08767570e-9f,  d1 = 1.60590438e-10f;
                const float d2 = 1.14707456e-11f, d3 = 7.64716373e-13f;
                const float d4 = 4.77947733e-14f;
                for (int idx = tid; idx < NPAULI; idx += NTHREADS) {
                    const int i = idx >> 6, j = idx & 63;
                    const int o = i * S + j;
                    float gr = d1 * Ar[o] + d2 * A2r[o] + d3 * A3r[o] + d4 * A4r[o];
                    float gi = d1 * Ai[o] + d2 * A2i[o] + d3 * A3i[o] + d4 * A4i[o];
                    if (i == j) gr += c0;
                    Br[o] = gr; Bi[o] = gi;
                }
                __syncthreads();
            }
            const signed char* d = c_ix[st];
            cmm_body(P12[d[0]], P12[d[1]], P12[d[2]], P12[d[3]],
                     P12[d[4]], P12[d[5]],
                     Ar, Ai, A2r, A2i, A3r, A3i,
                     d[6], c_cf[st][0], c_cf[st][1], c_cf[st][2], c_cf[st][3]);
            __syncthreads();
        }
        // U = (Cr, Ci)
        float* qr = Cr; float* qi = Ci;

        // ---- 6a. parameter job: publish Up and signal ----
        if (is_param) {
            for (int idx = tid; idx < DIM * DIM; idx += NTHREADS) {
                const int i = idx >> 6, j = idx & 63;
                g_Up[job][idx] = make_float2(qr[i * S + j], qi[i * S + j]);
            }
            __threadfence();
            __syncthreads();
            if (tid == 0) atomicAdd(&g_flag, 1);
            continue;
        }

        // ---- 6b. data job: wait for Up, run circuit ----
        if (tid == 0) {
            int v;
            do {
                asm volatile("ld.global.acquire.gpu.b32 %0, [%1];"
                             : "=r"(v) : "l"(&g_flag));
                if (v < nreps) __nanosleep(64);
            } while (v < nreps);
        }
        __threadfence();
        if (tid < DIM) psiA[tid] = make_float2(tid == 0 ? 1.f : 0.f, 0.f);
        __syncthreads();

        if (tid < 256) {
            float2* pin = psiA;
            float2* pout = psiB;
            const int row = tid >> 2, part = tid & 3;
            const int k0 = part * 16;

            for (int r = 0; r < nreps; r++) {
                {   // pout = Ud * pin  (Ud in smem planes qr/qi)
                    float sr = 0.f, si = 0.f;
#pragma unroll
                    for (int k = k0; k < k0 + 16; k++) {
                        const float mr = qr[row * S + k], mi = qi[row * S + k];
                        const float2 v = pin[k];
                        sr = fmaf(mr, v.x, sr); sr = fmaf(-mi, v.y, sr);
                        si = fmaf(mr, v.y, si); si = fmaf(mi, v.x, si);
                    }
                    sr += __shfl_xor_sync(0xffffffffu, sr, 1);
                    sr += __shfl_xor_sync(0xffffffffu, sr, 2);
                    si += __shfl_xor_sync(0xffffffffu, si, 1);
                    si += __shfl_xor_sync(0xffffffffu, si, 2);
                    if (part == 0) pout[row] = make_float2(sr, si);
                }
                __syncwarp();
                asm volatile("bar.sync 1, 256;" ::: "memory");
                { float2* t = pin; pin = pout; pout = t; }

                {   // pout = Up[r] * pin
                    const float2* U = g_Up[r];
                    float sr = 0.f, si = 0.f;
#pragma unroll
                    for (int k = k0; k < k0 + 16; k++) {
                        const float2 u = U[row * DIM + k];
                        const float2 v = pin[k];
                        sr = fmaf(u.x, v.x, sr); sr = fmaf(-u.y, v.y, sr);
                        si = fmaf(u.x, v.y, si); si = fmaf(u.y, v.x, si);
                    }
                    sr += __shfl_xor_sync(0xffffffffu, sr, 1);
                    sr += __shfl_xor_sync(0xffffffffu, sr, 2);
                    si += __shfl_xor_sync(0xffffffffu, si, 1);
                    si += __shfl_xor_sync(0xffffffffu, si, 2);
                    if (part == 0) pout[row] = make_float2(sr, si);
                }
                __syncwarp();
                asm volatile("bar.sync 1, 256;" ::: "memory");
                { float2* t = pin; pin = pout; pout = t; }
            }

            if (tid < DIM) {
                const float2 v = pin[tid];
                out[(size_t)(job - nreps) * DIM + tid] =
                    fmaf(v.x, v.x, v.y * v.y) + bias[tid];
            }
        }
    }
}

extern "C" void kernel_launch(void* const* d_in, const int* in_sizes, int n_in,
                              void* d_out, int out_size)
{
    const float* x      = (const float*)d_in[0];   // [512, 4000]
    const float* weight = (const float*)d_in[1];   // [4, 4095]
    const float* bias   = (const float*)d_in[2];   // [64]
    float* out = (float*)d_out;                    // [512, 64]

    const int B     = in_sizes[0] / 4000;
    const int nreps = in_sizes[1] / (NPAULI - 1);
    const int njobs = nreps + B;

    const size_t smem = (size_t)12 * PL * sizeof(float);   // 208,896 B
    cudaFuncSetAttribute(build_kernel,
                         cudaFuncAttributeMaxDynamicSharedMemorySize, (int)smem);

    reset_kernel<<<1, 1>>>();
    const int grid = (njobs < GRID) ? njobs : GRID;
    build_kernel<<<grid, NTHREADS, smem>>>(x, weight, bias, out, nreps, njobs);
}

// round 10
// speedup vs baseline: 1.2423x; 1.2423x over previous
#include <cuda_runtime.h>

// ---------------------------------------------------------------------------
// DataReUploadingLinear, Round 8:
//   R3's proven 2x4-tile cmm (static inlined pointers)  [387us champion]
// + deg-16 / s=6 expm: 12 matmuls                        [verified R5/R6]
// + persistent CTAs, fused circuit via flag spin         [verified R5/R6]
// + manual 2-stage software pipeline in cmm (static, explicit A/B regs)
// ---------------------------------------------------------------------------

#define DIM      64
#define NPAULI   4096
#define S        68                  // smem row stride (rows 16B-aligned)
#define PL       (64 * S)            // plane floats (4352)
#define NTHREADS 512
#define INV_SCALE (1.0f / 64.0f)     // 1 / 2^s, s = 6
#define GRID     152

typedef unsigned long long u64;

__device__ float2 g_Up[4][DIM * DIM];
__device__ int    g_flag;            // finished param jobs
__device__ int    g_ctr;             // persistent job counter

__device__ __forceinline__ u64 pk2(float lo, float hi) {
    u64 r; asm("mov.b64 %0, {%1, %2};" : "=l"(r) : "f"(lo), "f"(hi)); return r;
}
__device__ __forceinline__ u64 f2fma(u64 a, u64 b, u64 c) {
    u64 d; asm("fma.rn.f32x2 %0, %1, %2, %3;" : "=l"(d) : "l"(a), "l"(b), "l"(c));
    return d;
}
__device__ __forceinline__ u64 f2sub(u64 a, u64 b) {
    float al, ah, bl, bh;
    asm("mov.b64 {%0, %1}, %2;" : "=f"(al), "=f"(ah) : "l"(a));
    asm("mov.b64 {%0, %1}, %2;" : "=f"(bl), "=f"(bh) : "l"(b));
    return pk2(al - bl, ah - bh);
}

// Z = [G(A)] + X*Y, complex 64x64 in smem planes (stride S). 512 threads.
// Tile 2 rows x 4 cols (R3 layout). 2-stage software pipeline over 2-k
// blocks: stage-B loads issue before stage-A FMAs consume, and vice versa.
template <bool WITHG>
__device__ __forceinline__ void cmm(
    const float* __restrict__ Xr, const float* __restrict__ Xi,
    const float* __restrict__ Yr, const float* __restrict__ Yi,
    float* __restrict__ Zr, float* __restrict__ Zi,
    const float* __restrict__ Ar, const float* __restrict__ Ai,
    const float* __restrict__ A2r, const float* __restrict__ A2i,
    const float* __restrict__ A3r, const float* __restrict__ A3i,
    float c0, float c1, float c2, float c3)
{
    const int tid = threadIdx.x;
    const int ty = tid >> 4, tx = tid & 15;
    const int i0 = ty * 2, j0 = tx * 4;

    u64 crp[2][2], crn[2][2], cim[2][2];
#pragma unroll
    for (int a = 0; a < 2; a++)
#pragma unroll
        for (int p = 0; p < 2; p++) {
            if (WITHG) {
                const int i = i0 + a, j = j0 + 2 * p;
                const int o0 = i * S + j, o1 = o0 + 1;
                float g0r = c1 * Ar[o0] + c2 * A2r[o0] + c3 * A3r[o0]
                          + ((i == j)     ? c0 : 0.f);
                float g1r = c1 * Ar[o1] + c2 * A2r[o1] + c3 * A3r[o1]
                          + ((i == j + 1) ? c0 : 0.f);
                float g0i = c1 * Ai[o0] + c2 * A2i[o0] + c3 * A3i[o0];
                float g1i = c1 * Ai[o1] + c2 * A2i[o1] + c3 * A3i[o1];
                crp[a][p] = pk2(g0r, g1r);
                cim[a][p] = pk2(g0i, g1i);
            } else {
                crp[a][p] = 0ull; cim[a][p] = 0ull;
            }
            crn[a][p] = 0ull;
        }

    // pipeline registers: stage A and stage B, each = 2 consecutive k's
    float2 xrA[2], xiA[2], xrB[2], xiB[2];       // X: rows i0,i0+1, 2 k's
    u64 yrA[2][2], yiA[2][2], yrB[2][2], yiB[2][2];  // Y: [kk][colpair]

    // prologue: load stage A = k {0,1}
#pragma unroll
    for (int a = 0; a < 2; a++) {
        xrA[a] = *(const float2*)&Xr[(i0 + a) * S];
        xiA[a] = *(const float2*)&Xi[(i0 + a) * S];
    }
#pragma unroll
    for (int kk = 0; kk < 2; kk++) {
        const ulonglong2 r2 = *(const ulonglong2*)&Yr[kk * S + j0];
        const ulonglong2 q2 = *(const ulonglong2*)&Yi[kk * S + j0];
        yrA[kk][0] = r2.x; yrA[kk][1] = r2.y;
        yiA[kk][0] = q2.x; yiA[kk][1] = q2.y;
    }

#pragma unroll 1
    for (int k = 0; k < 64; k += 4) {
        // load stage B = {k+2, k+3}
#pragma unroll
        for (int a = 0; a < 2; a++) {
            xrB[a] = *(const float2*)&Xr[(i0 + a) * S + k + 2];
            xiB[a] = *(const float2*)&Xi[(i0 + a) * S + k + 2];
        }
#pragma unroll
        for (int kk = 0; kk < 2; kk++) {
            const ulonglong2 r2 = *(const ulonglong2*)&Yr[(k + 2 + kk) * S + j0];
            const ulonglong2 q2 = *(const ulonglong2*)&Yi[(k + 2 + kk) * S + j0];
            yrB[kk][0] = r2.x; yrB[kk][1] = r2.y;
            yiB[kk][0] = q2.x; yiB[kk][1] = q2.y;
        }
        // compute stage A = {k, k+1}
#pragma unroll
        for (int kk = 0; kk < 2; kk++)
#pragma unroll
            for (int a = 0; a < 2; a++) {
                const float xr = kk ? xrA[a].y : xrA[a].x;
                const float xi = kk ? xiA[a].y : xiA[a].x;
                const u64 xrr = pk2(xr, xr);
                const u64 xii = pk2(xi, xi);
#pragma unroll
                for (int p = 0; p < 2; p++) {
                    crp[a][p] = f2fma(xrr, yrA[kk][p], crp[a][p]);
                    crn[a][p] = f2fma(xii, yiA[kk][p], crn[a][p]);
                    cim[a][p] = f2fma(xrr, yiA[kk][p], cim[a][p]);
                    cim[a][p] = f2fma(xii, yrA[kk][p], cim[a][p]);
                }
            }
        // load stage A = {k+4, k+5}  (wraps harmlessly at k=60)
        {
            const int kn = (k + 4) & 63;
#pragma unroll
            for (int a = 0; a < 2; a++) {
                xrA[a] = *(const float2*)&Xr[(i0 + a) * S + kn];
                xiA[a] = *(const float2*)&Xi[(i0 + a) * S + kn];
            }
#pragma unroll
            for (int kk = 0; kk < 2; kk++) {
                const ulonglong2 r2 = *(const ulonglong2*)&Yr[(kn + kk) * S + j0];
                const ulonglong2 q2 = *(const ulonglong2*)&Yi[(kn + kk) * S + j0];
                yrA[kk][0] = r2.x; yrA[kk][1] = r2.y;
                yiA[kk][0] = q2.x; yiA[kk][1] = q2.y;
            }
        }
        // compute stage B = {k+2, k+3}
#pragma unroll
        for (int kk = 0; kk < 2; kk++)
#pragma unroll
            for (int a = 0; a < 2; a++) {
                const float xr = kk ? xrB[a].y : xrB[a].x;
                const float xi = kk ? xiB[a].y : xiB[a].x;
                const u64 xrr = pk2(xr, xr);
                const u64 xii = pk2(xi, xi);
#pragma unroll
                for (int p = 0; p < 2; p++) {
                    crp[a][p] = f2fma(xrr, yrB[kk][p], crp[a][p]);
                    crn[a][p] = f2fma(xii, yiB[kk][p], crn[a][p]);
                    cim[a][p] = f2fma(xrr, yiB[kk][p], cim[a][p]);
                    cim[a][p] = f2fma(xii, yrB[kk][p], cim[a][p]);
                }
            }
    }

#pragma unroll
    for (int a = 0; a < 2; a++)
#pragma unroll
        for (int p = 0; p < 2; p++) {
            *(u64*)&Zr[(i0 + a) * S + j0 + 2 * p] = f2sub(crp[a][p], crn[a][p]);
            *(u64*)&Zi[(i0 + a) * S + j0 + 2 * p] = cim[a][p];
        }
}

__global__ void reset_kernel() { g_flag = 0; g_ctr = 0; }

// Persistent: job < nreps -> build Up[job]; else build Ud for sample
// (job - nreps), wait for all Up, run circuit, write out.
__global__ __launch_bounds__(NTHREADS, 1)
void build_kernel(const float* __restrict__ x,
                  const float* __restrict__ weight,
                  const float* __restrict__ bias,
                  float* __restrict__ out,
                  int nreps, int njobs)
{
    extern __shared__ float sm[];
    float* Ar  = sm + 0 * PL;  float* Ai  = sm + 1 * PL;
    float* A2r = sm + 2 * PL;  float* A2i = sm + 3 * PL;
    float* A3r = sm + 4 * PL;  float* A3i = sm + 5 * PL;
    float* A4r = sm + 6 * PL;  float* A4i = sm + 7 * PL;
    float* Br  = sm + 8 * PL;  float* Bi  = sm + 9 * PL;
    float* Cr  = sm + 10 * PL; float* Ci  = sm + 11 * PL;
    __shared__ float2 psiA[DIM], psiB[DIM];
    __shared__ int s_job;

    const int tid = threadIdx.x;

    for (;;) {
        __syncthreads();                    // smem reuse + s_job protect
        if (tid == 0) s_job = atomicAdd(&g_ctr, 1);
        __syncthreads();
        const int job = s_job;
        if (job >= njobs) return;
        const bool is_param = (job < nreps);

        // ---- 1. Pauli coefficients into Br[0..4095] ----
        if (is_param) {
            const float* wrow = weight + (size_t)job * (NPAULI - 1);
            for (int p = tid; p < NPAULI; p += NTHREADS)
                Br[p] = (p == 0) ? 0.f : wrow[p - 1];
        } else {
            const float* xrow = x + (size_t)(job - nreps) * 4000;
            for (int p = tid; p < NPAULI; p += NTHREADS)
                Br[p] = (p < 4000) ? xrow[p] : 0.f;
        }
        __syncthreads();

        // ---- 2. D[m][t] = coef(p(m,t)) * (-i)^popc(t&m) ----
        for (int idx = tid; idx < NPAULI; idx += NTHREADS) {
            const int m = idx >> 6, t = idx & 63;
            const int mt = m ^ t;
            int p = 0;
#pragma unroll
            for (int k = 0; k < 6; k++)
                p |= (((mt >> k) & 1) << (2 * k)) | (((t >> k) & 1) << (2 * k + 1));
            const float v = Br[p];
            const int c = __popc(t & m) & 3;
            float re, im;
            switch (c) {
                case 0:  re =  v; im = 0.f; break;
                case 1:  re = 0.f; im = -v; break;
                case 2:  re = -v; im = 0.f; break;
                default: re = 0.f; im =  v; break;
            }
            Cr[idx] = re; Ci[idx] = im;
        }
        __syncthreads();

        // ---- 3. 64-pt WHT over t for each m ----
        for (int s = 0; s < 6; s++) {
            const int half = 1 << s;
            for (int n = tid; n < 2048; n += NTHREADS) {
                const int m = n >> 5, r = n & 31;
                const int t0 = ((r >> s) << (s + 1)) | (r & (half - 1));
                const int a0 = m * 64 + t0, a1 = a0 + half;
                const float ur = Cr[a0], ui = Ci[a0];
                const float vr = Cr[a1], vi = Ci[a1];
                Cr[a0] = ur + vr; Ci[a0] = ui + vi;
                Cr[a1] = ur - vr; Ci[a1] = ui - vi;
            }
            __syncthreads();
        }

        // ---- 4. A = -i*H/2^s :  H[i][i^m] = W[m][i] ----
        for (int idx = tid; idx < NPAULI; idx += NTHREADS) {
            const int m = idx >> 6, i = idx & 63;
            const int j = i ^ m;
            const float hr = Cr[m * 64 + i], hi = Ci[m * 64 + i];
            Ar[i * S + j] =  hi * INV_SCALE;
            Ai[i * S + j] = -hr * INV_SCALE;
        }
        __syncthreads();

        // ---- 5. powers A2, A3, A4 ----
        cmm<false>(Ar, Ai, Ar, Ai, A2r, A2i,
                   Ar, Ai, A2r, A2i, A3r, A3i, 0, 0, 0, 0);
        __syncthreads();
        cmm<false>(Ar, Ai, A2r, A2i, A3r, A3i,
                   Ar, Ai, A2r, A2i, A3r, A3i, 0, 0, 0, 0);
        __syncthreads();
        cmm<false>(A2r, A2i, A2r, A2i, A4r, A4i,
                   Ar, Ai, A2r, A2i, A3r, A3i, 0, 0, 0, 0);
        __syncthreads();

        // ---- 6. degree-16 PS with A4 blocks ----
        {   // B = G3 = I/12! + A/13! + A2/14! + A3/15! + A4/16!
            const float c0 = 2.08767570e-9f,  d1 = 1.60590438e-10f;
            const float d2 = 1.14707456e-11f, d3 = 7.64716373e-13f;
            const float d4 = 4.77947733e-14f;
            for (int idx = tid; idx < NPAULI; idx += NTHREADS) {
                const int i = idx >> 6, j = idx & 63;
                const int o = i * S + j;
                float gr = d1 * Ar[o] + d2 * A2r[o] + d3 * A3r[o] + d4 * A4r[o];
                float gi = d1 * Ai[o] + d2 * A2i[o] + d3 * A3i[o] + d4 * A4i[o];
                if (i == j) gr += c0;
                Br[o] = gr; Bi[o] = gi;
            }
        }
        __syncthreads();
        // C = G2 + A4*B   (I/8! + A/9! + A2/10! + A3/11!)
        cmm<true>(A4r, A4i, Br, Bi, Cr, Ci, Ar, Ai, A2r, A2i, A3r, A3i,
                  2.48015873e-5f, 2.75573192e-6f, 2.75573192e-7f, 2.50521084e-8f);
        __syncthreads();
        // B = G1 + A4*C   (I/4! + A/5! + A2/6! + A3/7!)
        cmm<true>(A4r, A4i, Cr, Ci, Br, Bi, Ar, Ai, A2r, A2i, A3r, A3i,
                  4.16666667e-2f, 8.33333333e-3f, 1.38888889e-3f, 1.98412698e-4f);
        __syncthreads();
        // C = G0 + A4*B   (I + A + A2/2 + A3/6)
        cmm<true>(A4r, A4i, Br, Bi, Cr, Ci, Ar, Ai, A2r, A2i, A3r, A3i,
                  1.f, 1.f, 0.5f, 1.f / 6.f);
        __syncthreads();

        // ---- 7. 6 squarings, ping-pong C <-> B (ends in C) ----
        float *qr = Cr, *qi = Ci, *pr = Br, *pi = Bi;
#pragma unroll 1
        for (int q = 0; q < 6; q++) {
            cmm<false>(qr, qi, qr, qi, pr, pi,
                       Ar, Ai, A2r, A2i, A3r, A3i, 0, 0, 0, 0);
            __syncthreads();
            float* t;
            t = qr; qr = pr; pr = t;
            t = qi; qi = pi; pi = t;
        }

        // ---- 8a. parameter job: publish Up and signal ----
        if (is_param) {
            for (int idx = tid; idx < DIM * DIM; idx += NTHREADS) {
                const int i = idx >> 6, j = idx & 63;
                g_Up[job][idx] = make_float2(qr[i * S + j], qi[i * S + j]);
            }
            __threadfence();
            __syncthreads();
            if (tid == 0) atomicAdd(&g_flag, 1);
            continue;
        }

        // ---- 8b. data job: wait for Up, run circuit ----
        if (tid == 0) {
            int v;
            do {
                asm volatile("ld.global.acquire.gpu.b32 %0, [%1];"
                             : "=r"(v) : "l"(&g_flag));
                if (v < nreps) __nanosleep(64);
            } while (v < nreps);
        }
        __threadfence();
        if (tid < DIM) psiA[tid] = make_float2(tid == 0 ? 1.f : 0.f, 0.f);
        __syncthreads();

        if (tid < 256) {
            float2* pin = psiA;
            float2* pout = psiB;
            const int row = tid >> 2, part = tid & 3;
            const int k0 = part * 16;

            for (int r = 0; r < nreps; r++) {
                {   // pout = Ud * pin  (Ud in smem planes qr/qi)
                    float sr = 0.f, si = 0.f;
#pragma unroll
                    for (int k = k0; k < k0 + 16; k++) {
                        const float mr = qr[row * S + k], mi = qi[row * S + k];
                        const float2 v = pin[k];
                        sr = fmaf(mr, v.x, sr); sr = fmaf(-mi, v.y, sr);
                        si = fmaf(mr, v.y, si); si = fmaf(mi, v.x, si);
                    }
                    sr += __shfl_xor_sync(0xffffffffu, sr, 1);
                    sr += __shfl_xor_sync(0xffffffffu, sr, 2);
                    si += __shfl_xor_sync(0xffffffffu, si, 1);
                    si += __shfl_xor_sync(0xffffffffu, si, 2);
                    if (part == 0) pout[row] = make_float2(sr, si);
                }
                __syncwarp();
                asm volatile("bar.sync 1, 256;" ::: "memory");
                { float2* t = pin; pin = pout; pout = t; }

                {   // pout = Up[r] * pin
                    const float2* U = g_Up[r];
                    float sr = 0.f, si = 0.f;
#pragma unroll
                    for (int k = k0; k < k0 + 16; k++) {
                        const float2 u = U[row * DIM + k];
                        const float2 v = pin[k];
                        sr = fmaf(u.x, v.x, sr); sr = fmaf(-u.y, v.y, sr);
                        si = fmaf(u.x, v.y, si); si = fmaf(u.y, v.x, si);
                    }
                    sr += __shfl_xor_sync(0xffffffffu, sr, 1);
                    sr += __shfl_xor_sync(0xffffffffu, sr, 2);
                    si += __shfl_xor_sync(0xffffffffu, si, 1);
                    si += __shfl_xor_sync(0xffffffffu, si, 2);
                    if (part == 0) pout[row] = make_float2(sr, si);
                }
                __syncwarp();
                asm volatile("bar.sync 1, 256;" ::: "memory");
                { float2* t = pin; pin = pout; pout = t; }
            }

            if (tid < DIM) {
                const float2 v = pin[tid];
                out[(size_t)(job - nreps) * DIM + tid] =
                    fmaf(v.x, v.x, v.y * v.y) + bias[tid];
            }
        }
    }
}

extern "C" void kernel_launch(void* const* d_in, const int* in_sizes, int n_in,
                              void* d_out, int out_size)
{
    const float* x      = (const float*)d_in[0];   // [512, 4000]
    const float* weight = (const float*)d_in[1];   // [4, 4095]
    const float* bias   = (const float*)d_in[2];   // [64]
    float* out = (float*)d_out;                    // [512, 64]

    const int B     = in_sizes[0] / 4000;
    const int nreps = in_sizes[1] / (NPAULI - 1);
    const int njobs = nreps + B;

    const size_t smem = (size_t)12 * PL * sizeof(float);   // 208,896 B
    cudaFuncSetAttribute(build_kernel,
                         cudaFuncAttributeMaxDynamicSharedMemorySize, (int)smem);

    reset_kernel<<<1, 1>>>();
    const int grid = (njobs < GRID) ? njobs : GRID;
    build_kernel<<<grid, NTHREADS, smem>>>(x, weight, bias, out, nreps, njobs);
}